// round 1
// baseline (speedup 1.0000x reference)
#include <cuda_runtime.h>

// Problem constants
#define NB   4096          // B
#define N2   8192          // 2B
#define DDIM 256           // feature dim
// (1/TEMP) * log2(e) : exp(s/T) == exp2(s * SCALE)
#define SCALE 2.8853900817779268f

// Scratch (device globals: no allocation allowed in kernel_launch)
__device__ float g_z[N2 * DDIM];   // normalized [2B, D]  (8 MB, L2-resident)
__device__ float g_denom[N2];      // per-row sum_{j!=i} exp(sim/T)
__device__ float g_loss;           // scalar accumulator

// ---------------------------------------------------------------------------
// Kernel 1: L2 normalize rows of [x_i ; x_j] into g_z. Also zeroes accumulators.
// One block (256 threads) per row.
// ---------------------------------------------------------------------------
__global__ __launch_bounds__(256) void k_norm(const float* __restrict__ xi,
                                              const float* __restrict__ xj) {
    const int row  = blockIdx.x;
    const int t    = threadIdx.x;
    const int lane = t & 31;
    const int warp = t >> 5;

    const float* src = (row < NB) ? (xi + (size_t)row * DDIM)
                                  : (xj + (size_t)(row - NB) * DDIM);
    float v = src[t];

    float s = v * v;
    #pragma unroll
    for (int o = 16; o; o >>= 1) s += __shfl_xor_sync(0xffffffffu, s, o);

    __shared__ float ws[8];
    __shared__ float inv;
    if (lane == 0) ws[warp] = s;
    __syncthreads();
    if (t == 0) {
        float tot = 0.f;
        #pragma unroll
        for (int w = 0; w < 8; ++w) tot += ws[w];
        float n = sqrtf(tot);
        inv = 1.0f / fmaxf(n, 1e-12f);   // matches F.normalize eps semantics
        g_denom[row] = 0.0f;
        if (row == 0) g_loss = 0.0f;
    }
    __syncthreads();
    g_z[(size_t)row * DDIM + t] = v * inv;
}

// ---------------------------------------------------------------------------
// Kernel 2: fused  sim = z z^T  ->  exp(sim/T) (diag masked)  -> row sums.
// Block: 256 threads as 16x16, each thread owns a 4x4 micro-tile -> 64x64 tile.
// Grid: (4 column groups, 128 row tiles). Each block sweeps 32 column tiles
// (2048 cols) keeping per-row partial denom in registers; one atomicAdd per
// row per block (32K atomics total).
// ---------------------------------------------------------------------------
__global__ __launch_bounds__(256) void k_gemm() {
    __shared__ float As[16][68];   // [k][row], padded: float4-aligned, low conflict
    __shared__ float Bs[16][68];   // [k][col]

    const int tid = threadIdx.x;
    const int tx  = tid & 15;
    const int ty  = tid >> 4;
    const int ty4 = ty * 4;
    const int tx4 = tx * 4;
    const int rowBase = blockIdx.y * 64;

    float dacc[4] = {0.f, 0.f, 0.f, 0.f};

    const int ct0 = blockIdx.x * 32;
    for (int ct = ct0; ct < ct0 + 32; ++ct) {
        const int colBase = ct * 64;

        float acc[4][4];
        #pragma unroll
        for (int i = 0; i < 4; ++i)
            #pragma unroll
            for (int j = 0; j < 4; ++j) acc[i][j] = 0.f;

        for (int k0 = 0; k0 < DDIM; k0 += 16) {
            __syncthreads();   // protect smem from previous iteration's readers
            // stage 64 rows x 16 k  for both operands (1024 floats each)
            for (int e = tid; e < 1024; e += 256) {
                const int r  = e >> 4;
                const int kk = e & 15;
                As[kk][r] = g_z[(size_t)(rowBase + r) * DDIM + k0 + kk];
                Bs[kk][r] = g_z[(size_t)(colBase + r) * DDIM + k0 + kk];
            }
            __syncthreads();

            #pragma unroll
            for (int kk = 0; kk < 16; ++kk) {
                const float4 a = *(const float4*)&As[kk][ty4];
                const float4 b = *(const float4*)&Bs[kk][tx4];
                acc[0][0] = fmaf(a.x, b.x, acc[0][0]);
                acc[0][1] = fmaf(a.x, b.y, acc[0][1]);
                acc[0][2] = fmaf(a.x, b.z, acc[0][2]);
                acc[0][3] = fmaf(a.x, b.w, acc[0][3]);
                acc[1][0] = fmaf(a.y, b.x, acc[1][0]);
                acc[1][1] = fmaf(a.y, b.y, acc[1][1]);
                acc[1][2] = fmaf(a.y, b.z, acc[1][2]);
                acc[1][3] = fmaf(a.y, b.w, acc[1][3]);
                acc[2][0] = fmaf(a.z, b.x, acc[2][0]);
                acc[2][1] = fmaf(a.z, b.y, acc[2][1]);
                acc[2][2] = fmaf(a.z, b.z, acc[2][2]);
                acc[2][3] = fmaf(a.z, b.w, acc[2][3]);
                acc[3][0] = fmaf(a.w, b.x, acc[3][0]);
                acc[3][1] = fmaf(a.w, b.y, acc[3][1]);
                acc[3][2] = fmaf(a.w, b.z, acc[3][2]);
                acc[3][3] = fmaf(a.w, b.w, acc[3][3]);
            }
        }

        // epilogue: exp(sim/T) with diagonal masked, accumulate row sums
        #pragma unroll
        for (int i = 0; i < 4; ++i) {
            const int gr = rowBase + ty4 + i;
            float rs = 0.f;
            #pragma unroll
            for (int j = 0; j < 4; ++j) {
                float e;
                const float v = acc[i][j] * SCALE;
                asm("ex2.approx.f32 %0, %1;" : "=f"(e) : "f"(v));
                if (gr == colBase + tx4 + j) e = 0.f;   // mask j == i
                rs += e;
            }
            dacc[i] += rs;
        }
    }

    // reduce denom across the 16 tx lanes (xor of lane bits 0..3 stays in-row)
    #pragma unroll
    for (int i = 0; i < 4; ++i) {
        #pragma unroll
        for (int o = 8; o; o >>= 1)
            dacc[i] += __shfl_xor_sync(0xffffffffu, dacc[i], o);
    }
    if (tx == 0) {
        #pragma unroll
        for (int i = 0; i < 4; ++i)
            atomicAdd(&g_denom[rowBase + ty4 + i], dacc[i]);
    }
}

// ---------------------------------------------------------------------------
// Kernel 3: per-row loss  -pos/T + log(denom), reduced into g_loss.
// One warp per row (pos_i = z_i . z_{(i+B) mod 2B}), 8 rows per block.
// ---------------------------------------------------------------------------
__global__ __launch_bounds__(256) void k_rowloss() {
    const int lane = threadIdx.x & 31;
    const int warp = threadIdx.x >> 5;
    const int row  = blockIdx.x * 8 + warp;

    const float* zi = g_z + (size_t)row * DDIM;
    const float* zp = g_z + (size_t)((row + NB) & (N2 - 1)) * DDIM;

    float p = 0.f;
    #pragma unroll
    for (int c = 0; c < 8; ++c) {
        const int idx = c * 32 + lane;
        p = fmaf(zi[idx], zp[idx], p);
    }
    #pragma unroll
    for (int o = 16; o; o >>= 1) p += __shfl_xor_sync(0xffffffffu, p, o);

    __shared__ float ps[8];
    if (lane == 0) ps[warp] = fmaf(-2.0f, p, logf(g_denom[row]));  // 1/T = 2
    __syncthreads();
    if (threadIdx.x == 0) {
        float s = 0.f;
        #pragma unroll
        for (int w = 0; w < 8; ++w) s += ps[w];
        atomicAdd(&g_loss, s);
    }
}

__global__ void k_final(float* __restrict__ out) {
    out[0] = g_loss * (1.0f / (float)N2);
}

// ---------------------------------------------------------------------------
extern "C" void kernel_launch(void* const* d_in, const int* in_sizes, int n_in,
                              void* d_out, int out_size) {
    const float* xi = (const float*)d_in[0];
    const float* xj = (const float*)d_in[1];
    float* out = (float*)d_out;

    k_norm<<<N2, 256>>>(xi, xj);
    dim3 grid(4, 128);
    k_gemm<<<grid, 256>>>();
    k_rowloss<<<N2 / 8, 256>>>();
    k_final<<<1, 1>>>(out);
}

// round 14
// speedup vs baseline: 10.9378x; 10.9378x over previous
#include <cuda_runtime.h>
#include <cuda_bf16.h>
#include <cstdint>

// Problem constants
#define NB   4096
#define N2   8192
#define DDIM 256
// (1/TEMP) * log2(e): exp(s/T) == exp2(s * SCALE)
#define SCALE 2.8853900817779268f

// Device scratch (no allocations allowed)
__device__ float g_z[N2 * DDIM];                        // fp32 normalized (pos dot)
__device__ __align__(16) __nv_bfloat16 g_zb[N2 * DDIM]; // bf16 normalized (MMA operand)
__device__ float g_denom[N2];

// ---------------------------------------------------------------------------
// Helpers (baseline PTX only: ldmatrix / mma.sync / cp.async — all OK at compute_103)
// ---------------------------------------------------------------------------
__device__ __forceinline__ uint32_t smem_u32(const void* p) {
    uint32_t a;
    asm("{ .reg .u64 t; cvta.to.shared.u64 t, %1; cvt.u32.u64 %0, t; }" : "=r"(a) : "l"(p));
    return a;
}

#define CP_ASYNC16(dst, src) \
    asm volatile("cp.async.cg.shared.global [%0], [%1], 16;" :: "r"(dst), "l"(src) : "memory")
#define CP_COMMIT() asm volatile("cp.async.commit_group;" ::: "memory")
#define CP_WAIT(n)  asm volatile("cp.async.wait_group %0;" :: "n"(n) : "memory")

__device__ __forceinline__ void ldsm_x4(uint32_t& r0, uint32_t& r1, uint32_t& r2, uint32_t& r3,
                                        uint32_t addr) {
    asm volatile("ldmatrix.sync.aligned.m8n8.x4.shared.b16 {%0,%1,%2,%3}, [%4];"
                 : "=r"(r0), "=r"(r1), "=r"(r2), "=r"(r3) : "r"(addr));
}
__device__ __forceinline__ void ldsm_x2(uint32_t& r0, uint32_t& r1, uint32_t addr) {
    asm volatile("ldmatrix.sync.aligned.m8n8.x2.shared.b16 {%0,%1}, [%2];"
                 : "=r"(r0), "=r"(r1) : "r"(addr));
}
__device__ __forceinline__ void mma16816(float* d, const uint32_t* a, const uint32_t* b) {
    asm volatile(
        "mma.sync.aligned.m16n8k16.row.col.f32.bf16.bf16.f32 "
        "{%0,%1,%2,%3}, {%4,%5,%6,%7}, {%8,%9}, {%0,%1,%2,%3};"
        : "+f"(d[0]), "+f"(d[1]), "+f"(d[2]), "+f"(d[3])
        : "r"(a[0]), "r"(a[1]), "r"(a[2]), "r"(a[3]), "r"(b[0]), "r"(b[1]));
}

// Tile rows are 512B (256 bf16). XOR-swizzle 16B chunks so ldmatrix's 8 row
// pointers (stride 512B) land in 8 distinct 16B banks of a 128B line.
__device__ __forceinline__ uint32_t swz(int r, int kb) {
    return ((uint32_t)r << 9) + ((uint32_t)kb ^ (((uint32_t)(r & 7)) << 4));
}

// SMEM layout: A tile 64KB @0, B tiles 64KB @65536 / @131072
#define SM_B     65536
#define SM_TOTAL 196608

// ---------------------------------------------------------------------------
// Kernel 1: L2-normalize; write fp32 + bf16 copies; zero accumulators.
// ---------------------------------------------------------------------------
__global__ __launch_bounds__(256) void k_norm(const float* __restrict__ xi,
                                              const float* __restrict__ xj,
                                              float* __restrict__ out) {
    const int row  = blockIdx.x;
    const int t    = threadIdx.x;
    const int lane = t & 31;
    const int warp = t >> 5;

    const float* src = (row < NB) ? (xi + (size_t)row * DDIM)
                                  : (xj + (size_t)(row - NB) * DDIM);
    float v = src[t];

    float s = v * v;
    #pragma unroll
    for (int o = 16; o; o >>= 1) s += __shfl_xor_sync(0xffffffffu, s, o);

    __shared__ float ws[8];
    __shared__ float inv;
    if (lane == 0) ws[warp] = s;
    __syncthreads();
    if (t == 0) {
        float tot = 0.f;
        #pragma unroll
        for (int w = 0; w < 8; ++w) tot += ws[w];
        inv = 1.0f / fmaxf(sqrtf(tot), 1e-12f);
        g_denom[row] = 0.0f;
        if (row == 0) out[0] = 0.0f;
    }
    __syncthreads();
    const float zv = v * inv;
    g_z[(size_t)row * DDIM + t]  = zv;
    g_zb[(size_t)row * DDIM + t] = __float2bfloat16(zv);
}

// ---------------------------------------------------------------------------
// Kernel 2: HMMA fused  sim = z z^T -> exp(sim/T) (diag masked) -> row sums.
// grid = 128: rowTile = bid>>1 (128 rows), column half = bid&1 (4096 cols).
// 256 threads = 8 warps in 2(m) x 4(n); warp tile 64x32; mma m16n8k16 bf16.
// A tile resident in SMEM; B tiles double-buffered via cp.async.
// ---------------------------------------------------------------------------
__global__ __launch_bounds__(256, 1) void k_sim() {
    extern __shared__ char smem[];
    const uint32_t sb = smem_u32(smem);
    const int tid  = threadIdx.x;
    const int lane = tid & 31;
    const int wid  = tid >> 5;
    const int wm   = wid >> 2;           // 0..1
    const int wn   = wid & 3;            // 0..3
    const int rowBase = (blockIdx.x >> 1) << 7;
    const int colHalf = (blockIdx.x & 1) * 4096;

    const char* zbytes = (const char*)g_zb;

    // Stage A tile [128 x 256] bf16 (cp.async, swizzled): 16 chunks of 16B/thread
    #pragma unroll
    for (int j = 0; j < 16; ++j) {
        const int i = tid + j * 256;
        const int r = i >> 5, kc = i & 31;
        CP_ASYNC16(sb + swz(r, kc * 16),
                   zbytes + ((size_t)(rowBase + r) * DDIM + kc * 8) * 2);
    }
    CP_COMMIT();

    // Prefetch B tile 0
    #pragma unroll
    for (int j = 0; j < 16; ++j) {
        const int i = tid + j * 256;
        const int r = i >> 5, kc = i & 31;
        CP_ASYNC16(sb + SM_B + swz(r, kc * 16),
                   zbytes + ((size_t)(colHalf + r) * DDIM + kc * 8) * 2);
    }
    CP_COMMIT();

    float rsum[8];
    #pragma unroll
    for (int k = 0; k < 8; ++k) rsum[k] = 0.f;

    // A-fragment ldmatrix base addresses (fixed per thread; k advances)
    const int aRow = wm * 64 + (lane & 15);
    const int aKb0 = (lane >> 4) * 16;

    for (int t = 0; t < 32; ++t) {
        if (t < 31) {
            const uint32_t bdst = sb + SM_B + (((t + 1) & 1) << 16);
            const size_t cb = (size_t)(colHalf + (t + 1) * 128);
            #pragma unroll
            for (int j = 0; j < 16; ++j) {
                const int i = tid + j * 256;
                const int r = i >> 5, kc = i & 31;
                CP_ASYNC16(bdst + swz(r, kc * 16),
                           zbytes + ((cb + r) * DDIM + kc * 8) * 2);
            }
            CP_COMMIT();
            CP_WAIT(1);
        } else {
            CP_WAIT(0);
        }
        __syncthreads();

        const uint32_t bbase = sb + SM_B + ((t & 1) << 16);
        float d[4][4][4];
        #pragma unroll
        for (int mi = 0; mi < 4; ++mi)
            #pragma unroll
            for (int nj = 0; nj < 4; ++nj)
                #pragma unroll
                for (int i = 0; i < 4; ++i) d[mi][nj][i] = 0.f;

        const int bRow = wn * 32 + (lane & 7);
        const int bKb0 = ((lane >> 3) & 1) * 16;

        #pragma unroll
        for (int ks = 0; ks < 16; ++ks) {
            uint32_t a[4][4];
            #pragma unroll
            for (int mi = 0; mi < 4; ++mi)
                ldsm_x4(a[mi][0], a[mi][1], a[mi][2], a[mi][3],
                        sb + swz(aRow + mi * 16, ks * 32 + aKb0));
            uint32_t b[4][2];
            #pragma unroll
            for (int nj = 0; nj < 4; ++nj)
                ldsm_x2(b[nj][0], b[nj][1],
                        bbase + swz(bRow + nj * 8, ks * 32 + bKb0));
            #pragma unroll
            for (int mi = 0; mi < 4; ++mi)
                #pragma unroll
                for (int nj = 0; nj < 4; ++nj)
                    mma16816(d[mi][nj], a[mi], b[nj]);
        }
        __syncthreads();   // all reads of this B buffer done before next overwrite

        // Epilogue: exp(sim/T), mask diagonal, accumulate per-row partials
        const int colT = colHalf + t * 128 + wn * 32 + (lane & 3) * 2;
        #pragma unroll
        for (int mi = 0; mi < 4; ++mi) {
            #pragma unroll
            for (int hi = 0; hi < 2; ++hi) {
                const int gr = rowBase + wm * 64 + mi * 16 + (lane >> 2) + hi * 8;
                float acc = 0.f;
                #pragma unroll
                for (int nj = 0; nj < 4; ++nj) {
                    const int gc = colT + nj * 8;
                    #pragma unroll
                    for (int c = 0; c < 2; ++c) {
                        float e;
                        const float x = d[mi][nj][hi * 2 + c] * SCALE;
                        asm("ex2.approx.f32 %0, %1;" : "=f"(e) : "f"(x));
                        if (gc + c == gr) e = 0.f;
                        acc += e;
                    }
                }
                rsum[mi * 2 + hi] += acc;
            }
        }
    }

    // Reduce row partials across the 4 lanes sharing the same rows
    #pragma unroll
    for (int k = 0; k < 8; ++k) {
        rsum[k] += __shfl_xor_sync(0xffffffffu, rsum[k], 1);
        rsum[k] += __shfl_xor_sync(0xffffffffu, rsum[k], 2);
    }
    if ((lane & 3) == 0) {
        #pragma unroll
        for (int k = 0; k < 8; ++k) {
            const int row = rowBase + wm * 64 + (k >> 1) * 16 + (lane >> 2) + (k & 1) * 8;
            atomicAdd(&g_denom[row], rsum[k]);
        }
    }
}

// ---------------------------------------------------------------------------
// Kernel 3: per-row loss  -2*pos + log(denom), reduced straight into out[0].
// ---------------------------------------------------------------------------
__global__ __launch_bounds__(256) void k_rowloss(float* __restrict__ out) {
    const int lane = threadIdx.x & 31;
    const int warp = threadIdx.x >> 5;
    const int row  = blockIdx.x * 8 + warp;

    const float* zi = g_z + (size_t)row * DDIM;
    const float* zp = g_z + (size_t)((row + NB) & (N2 - 1)) * DDIM;

    float p = 0.f;
    #pragma unroll
    for (int c = 0; c < 8; ++c) {
        const int idx = c * 32 + lane;
        p = fmaf(zi[idx], zp[idx], p);
    }
    #pragma unroll
    for (int o = 16; o; o >>= 1) p += __shfl_xor_sync(0xffffffffu, p, o);

    __shared__ float ps[8];
    if (lane == 0) ps[warp] = fmaf(-2.0f, p, logf(g_denom[row]));
    __syncthreads();
    if (threadIdx.x == 0) {
        float t = 0.f;
        #pragma unroll
        for (int w = 0; w < 8; ++w) t += ps[w];
        atomicAdd(out, t * (1.0f / (float)N2));
    }
}

// ---------------------------------------------------------------------------
extern "C" void kernel_launch(void* const* d_in, const int* in_sizes, int n_in,
                              void* d_out, int out_size) {
    const float* xi = (const float*)d_in[0];
    const float* xj = (const float*)d_in[1];
    float* out = (float*)d_out;

    cudaFuncSetAttribute(k_sim, cudaFuncAttributeMaxDynamicSharedMemorySize, SM_TOTAL);

    k_norm<<<N2, 256>>>(xi, xj, out);
    k_sim<<<128, 256, SM_TOTAL>>>();
    k_rowloss<<<N2 / 8, 256>>>(out);
}